// round 1
// baseline (speedup 1.0000x reference)
#include <cuda_runtime.h>

// MSFNO1d: B=32, L=4096, H=64, NL=4, modes {512,1024,2048}
// Pipeline per layer:  rfft(v) -> combined per-freq complex GEMM -> irfft -> pointwise MLP residual
#define BB 32
#define HH 64
#define LL 4096
#define NF 2048   // frequencies actually used (modes max); bin 2048 (Nyquist) is zero

typedef unsigned long long ull;

// ---- scratch (device globals; no allocation allowed) ----
__device__ float  g_v[BB*HH*LL];          // 33.5 MB  current features [b][h][t]
__device__ float  g_s[BB*HH*LL];          // 33.5 MB  spectral output  [b][h][t]
__device__ float2 g_X[HH*BB*NF];          // 33.5 MB  rfft(v)   layout [i][b][f]
__device__ float2 g_Y[HH*BB*NF];          // 33.5 MB  mixed     layout [o][b][f]
__device__ float2 g_tw2048[1024];         // e^{-2pi i k/2048}
__device__ float2 g_tw4096[2048];         // e^{-2pi i k/4096}

// ---- helpers ----
__device__ __forceinline__ float2 cmul(float2 a, float2 b){
    return make_float2(a.x*b.x - a.y*b.y, a.x*b.y + a.y*b.x);
}
__device__ __forceinline__ ull pack2(float lo, float hi){
    ull r; asm("mov.b64 %0,{%1,%2};" : "=l"(r) : "f"(lo), "f"(hi)); return r;
}
__device__ __forceinline__ float2 unpack2(ull v){
    float2 r; asm("mov.b64 {%0,%1},%2;" : "=f"(r.x), "=f"(r.y) : "l"(v)); return r;
}
__device__ __forceinline__ void fma2(ull &acc, ull a, ull b){
    asm("fma.rn.f32x2 %0,%1,%2,%0;" : "+l"(acc) : "l"(a), "l"(b));
}
__device__ __forceinline__ float gelu_tanh(float x){
    float x3 = x*x*x;
    return 0.5f*x*(1.0f + tanhf(0.7978845608028654f*(x + 0.044715f*x3)));
}

// ---- twiddle init (double precision for accuracy; runs every call, deterministic) ----
__global__ void init_tw_kernel(){
    int k = blockIdx.x*256 + threadIdx.x;
    if (k < 1024){
        double s, c; sincospi(-2.0*(double)k/2048.0, &s, &c);
        g_tw2048[k] = make_float2((float)c, (float)s);
    }
    if (k < 2048){
        double s, c; sincospi(-2.0*(double)k/4096.0, &s, &c);
        g_tw4096[k] = make_float2((float)c, (float)s);
    }
}

// ---- encoder: v[b,h,t] = enc_b[h] + enc_w[h,0]*x + enc_w[h,1..3]*u[0..2] ----
__global__ void encoder_kernel(const float* __restrict__ u, const float* __restrict__ x,
                               const float* __restrict__ ew, const float* __restrict__ eb){
    int b = blockIdx.y;
    int t = blockIdx.x*256 + threadIdx.x;
    float xv = x[(size_t)b*LL + t];
    float u0 = u[((size_t)b*3 + 0)*LL + t];
    float u1 = u[((size_t)b*3 + 1)*LL + t];
    float u2 = u[((size_t)b*3 + 2)*LL + t];
    #pragma unroll 4
    for (int h = 0; h < HH; h++){
        float r = eb[h] + ew[h*4+0]*xv + ew[h*4+1]*u0 + ew[h*4+2]*u1 + ew[h*4+3]*u2;
        g_v[((size_t)b*HH + h)*LL + t] = r;
    }
}

// ---- in-place 2048-pt radix-2 DIT complex FFT on shared memory (input bit-reversed) ----
__device__ void fft2048(float2* S){
    for (int s = 1; s <= 11; s++){
        int half  = 1 << (s-1);
        int tsh   = 11 - s;
        __syncthreads();
        for (int idx = threadIdx.x; idx < 1024; idx += 256){
            int j   = idx & (half-1);
            int pos = ((idx >> (s-1)) << s) + j;
            float2 w = g_tw2048[j << tsh];
            float2 a = S[pos], bv = S[pos+half];
            float2 t = cmul(w, bv);
            S[pos]      = make_float2(a.x + t.x, a.y + t.y);
            S[pos+half] = make_float2(a.x - t.x, a.y - t.y);
        }
    }
    __syncthreads();
}

// ---- forward rfft of v row (length 4096) via 2048-pt complex FFT; writes bins 0..2047 ----
__global__ void fft_fwd_kernel(){
    int b = blockIdx.x, i = blockIdx.y;
    __shared__ float2 S[2048];
    const float2* src = (const float2*)(g_v + ((size_t)b*HH + i)*LL);
    for (int n = threadIdx.x; n < 2048; n += 256)
        S[__brev((unsigned)n) >> 21] = src[n];            // z[n] = v[2n] + i v[2n+1]
    fft2048(S);
    float2* dst = g_X + ((size_t)i*BB + b)*NF;
    for (int k = threadIdx.x; k < 2048; k += 256){
        float2 Zk = S[k];
        float2 Zn = S[(2048 - k) & 2047];
        float2 Fe = make_float2(0.5f*(Zk.x + Zn.x),  0.5f*(Zk.y - Zn.y));
        float2 Fo = make_float2(0.5f*(Zk.y + Zn.y), -0.5f*(Zk.x - Zn.x));
        float2 w  = g_tw4096[k];
        float2 t  = cmul(w, Fo);
        dst[k] = make_float2(Fe.x + t.x, Fe.y + t.y);
    }
}

// ---- spectral mixing: Y[b,o,f] = sum_i X[b,i,f] * Wsum[i,o,f] ----
// block: f-tile 32 (lanes), o-tile 8; all b=32; loop i. W read exactly once, coalesced along f.
__global__ __launch_bounds__(512) void spec_gemm_kernel(const float* __restrict__ w0,
                                                        const float* __restrict__ w1,
                                                        const float* __restrict__ w2, int l){
    __shared__ float2 Ws[8*32];    // [oi][lane]
    __shared__ float2 Xs[32*32];   // [b][lane]
    int f0 = blockIdx.x * 32;
    int o0 = blockIdx.y * 8;
    int tid  = threadIdx.x;
    int lane = tid & 31;
    int g    = tid >> 5;           // 0..15
    int b0   = (g & 7) * 4;        // 4 b's per thread
    int oo   = (g >> 3) * 4;       // 4 o's per thread (within 8)
    bool p1 = (f0 < 1024), p0 = (f0 < 512);
    const float2* W2p = (const float2*)w2 + (size_t)l*HH*HH*2048;
    const float2* W1p = (const float2*)w1 + (size_t)l*HH*HH*1024;
    const float2* W0p = (const float2*)w0 + (size_t)l*HH*HH*512;

    ull acc[4][4];
    #pragma unroll
    for (int bi = 0; bi < 4; bi++)
        #pragma unroll
        for (int oi = 0; oi < 4; oi++) acc[bi][oi] = 0ull;   // bits of (0.f,0.f)

    for (int i = 0; i < HH; i++){
        if (tid < 256){
            int oi = tid >> 5;
            size_t base = (size_t)i*HH + (o0 + oi);
            float2 wv = W2p[base*2048 + f0 + lane];
            if (p1){ float2 a = W1p[base*1024 + f0 + lane]; wv.x += a.x; wv.y += a.y; }
            if (p0){ float2 a = W0p[base*512  + f0 + lane]; wv.x += a.x; wv.y += a.y; }
            Ws[tid] = wv;
        }
        {
            int bb = tid >> 5; // 0..15 -> loads b=bb and b=bb+16
            Xs[bb*32 + lane]      = g_X[((size_t)i*BB + bb     )*NF + f0 + lane];
            Xs[(bb+16)*32 + lane] = g_X[((size_t)i*BB + bb + 16)*NF + f0 + lane];
        }
        __syncthreads();
        ull wp[4], wn[4];
        #pragma unroll
        for (int oi = 0; oi < 4; oi++){
            float2 w = Ws[(oo + oi)*32 + lane];
            wp[oi] = pack2(w.x, w.y);
            wn[oi] = pack2(-w.y, w.x);
        }
        #pragma unroll
        for (int bi = 0; bi < 4; bi++){
            float2 xv = Xs[(b0 + bi)*32 + lane];
            ull xr = pack2(xv.x, xv.x);
            ull xi = pack2(xv.y, xv.y);
            #pragma unroll
            for (int oi = 0; oi < 4; oi++){
                fma2(acc[bi][oi], xr, wp[oi]);
                fma2(acc[bi][oi], xi, wn[oi]);
            }
        }
        __syncthreads();
    }
    #pragma unroll
    for (int bi = 0; bi < 4; bi++)
        #pragma unroll
        for (int oi = 0; oi < 4; oi++){
            float2 r = unpack2(acc[bi][oi]);
            g_Y[((size_t)(o0 + oo + oi)*BB + b0 + bi)*NF + f0 + lane] = r;
        }
}

// ---- inverse rfft (n=4096, bins>=2048 zero) + spectral bias; writes g_s ----
__global__ void fft_inv_kernel(const float* __restrict__ sb0, const float* __restrict__ sb1,
                               const float* __restrict__ sb2, int l){
    int b = blockIdx.x, o = blockIdx.y;
    __shared__ float2 S[2048];
    __shared__ float2 Q[2048];
    const float2* src = g_Y + ((size_t)o*BB + b)*NF;
    for (int k = threadIdx.x; k < 2048; k += 256) S[k] = src[k];
    __syncthreads();
    for (int k = threadIdx.x; k < 2048; k += 256){
        float2 Xk = S[k];
        float2 Xn;
        if (k == 0){ Xk.y = 0.0f; Xn = make_float2(0.0f, 0.0f); }  // c2r drops imag(bin0); X[2048]=0
        else        { Xn = S[2048 - k]; }
        float2 Fe = make_float2(0.5f*(Xk.x + Xn.x), 0.5f*(Xk.y - Xn.y));
        float2 D  = make_float2(0.5f*(Xk.x - Xn.x), 0.5f*(Xk.y + Xn.y));
        float2 w  = g_tw4096[k];                       // e^{-i th}; need e^{+i th} = conj
        float2 Fo = make_float2(D.x*w.x + D.y*w.y, D.y*w.x - D.x*w.y);
        float2 Zp = make_float2(Fe.x - Fo.y, Fe.y + Fo.x);
        Q[__brev((unsigned)k) >> 21] = make_float2(Zp.x, -Zp.y);   // conj -> forward FFT = IFFT trick
    }
    fft2048(Q);
    float bias = sb0[l*HH + o] + sb1[l*HH + o] + sb2[l*HH + o];
    float2* dst = (float2*)(g_s + ((size_t)b*HH + o)*LL);
    const float sc = 1.0f/2048.0f;
    for (int n = threadIdx.x; n < 2048; n += 256){
        float2 R = Q[n];
        dst[n] = make_float2(R.x*sc + bias, -R.y*sc + bias);       // conj back + 1/N
    }
}

// ---- pointwise: v += conv2( gelu( conv1(s) ) ) ; 64-wide t-tile per block ----
__global__ __launch_bounds__(256) void pointwise_kernel(const float* __restrict__ w1,
                                                        const float* __restrict__ b1,
                                                        const float* __restrict__ w2,
                                                        const float* __restrict__ b2, int l){
    int b  = blockIdx.y;
    int t0 = blockIdx.x * 64;
    __shared__ float ss[64][64];   // [i][t]
    __shared__ float hh[64][64];   // [o][t]
    __shared__ float Wb[64][64];   // weights (reused for W1 then W2)
    int tid = threadIdx.x;
    for (int idx = tid; idx < 4096; idx += 256) Wb[idx >> 6][idx & 63] = w1[(size_t)l*4096 + idx];
    for (int idx = tid; idx < 4096; idx += 256)
        ss[idx >> 6][idx & 63] = g_s[((size_t)b*HH + (idx >> 6))*LL + t0 + (idx & 63)];
    __syncthreads();

    int tp = tid & 31;     // t pair: t = 2*tp
    int oc = tid >> 5;     // 0..7 -> 8 output channels each
    #pragma unroll
    for (int oi = 0; oi < 8; oi++){
        int o = oc*8 + oi;
        float bb = b1[l*HH + o];
        ull acc = pack2(bb, bb);
        #pragma unroll 8
        for (int i = 0; i < 64; i++){
            float w = Wb[o][i];
            ull sv = *(const ull*)&ss[i][2*tp];
            fma2(acc, pack2(w, w), sv);
        }
        float2 a = unpack2(acc);
        hh[o][2*tp]   = gelu_tanh(a.x);
        hh[o][2*tp+1] = gelu_tanh(a.y);
    }
    __syncthreads();
    for (int idx = tid; idx < 4096; idx += 256) Wb[idx >> 6][idx & 63] = w2[(size_t)l*4096 + idx];
    __syncthreads();
    #pragma unroll
    for (int ci = 0; ci < 8; ci++){
        int c = oc*8 + ci;
        float bb = b2[l*HH + c];
        ull acc = pack2(bb, bb);
        #pragma unroll 8
        for (int o = 0; o < 64; o++){
            float w = Wb[c][o];
            ull hv = *(const ull*)&hh[o][2*tp];
            fma2(acc, pack2(w, w), hv);
        }
        float2 a = unpack2(acc);
        float2* vp = (float2*)(g_v + ((size_t)b*HH + c)*LL + t0 + 2*tp);
        float2 vv = *vp;
        vv.x += a.x; vv.y += a.y;
        *vp = vv;
    }
}

// ---- decoder: out[b,0,t] = dec_b + sum_h dec_w[h] * v[b,h,t] ----
__global__ void decoder_kernel(const float* __restrict__ dw, const float* __restrict__ db,
                               float* __restrict__ out){
    int b = blockIdx.y;
    int t = blockIdx.x*256 + threadIdx.x;
    float acc = db[0];
    #pragma unroll 8
    for (int h = 0; h < HH; h++)
        acc += dw[h] * g_v[((size_t)b*HH + h)*LL + t];
    out[(size_t)b*LL + t] = acc;
}

extern "C" void kernel_launch(void* const* d_in, const int* in_sizes, int n_in,
                              void* d_out, int out_size){
    const float* u     = (const float*)d_in[0];
    const float* x     = (const float*)d_in[1];
    const float* enc_w = (const float*)d_in[2];
    const float* enc_b = (const float*)d_in[3];
    const float* dec_w = (const float*)d_in[4];
    const float* dec_b = (const float*)d_in[5];
    const float* c1w   = (const float*)d_in[6];
    const float* c1b   = (const float*)d_in[7];
    const float* c2w   = (const float*)d_in[8];
    const float* c2b   = (const float*)d_in[9];
    const float* sw0   = (const float*)d_in[10];
    const float* sb0   = (const float*)d_in[11];
    const float* sw1   = (const float*)d_in[12];
    const float* sb1   = (const float*)d_in[13];
    const float* sw2   = (const float*)d_in[14];
    const float* sb2   = (const float*)d_in[15];
    float* out = (float*)d_out;

    init_tw_kernel<<<8, 256>>>();
    encoder_kernel<<<dim3(LL/256, BB), 256>>>(u, x, enc_w, enc_b);
    for (int l = 0; l < 4; l++){
        fft_fwd_kernel<<<dim3(BB, HH), 256>>>();
        spec_gemm_kernel<<<dim3(NF/32, HH/8), 512>>>(sw0, sw1, sw2, l);
        fft_inv_kernel<<<dim3(BB, HH), 256>>>(sb0, sb1, sb2, l);
        pointwise_kernel<<<dim3(LL/64, BB), 256>>>(c1w, c1b, c2w, c2b, l);
    }
    decoder_kernel<<<dim3(LL/256, BB), 256>>>(dec_w, dec_b, out);
}

// round 2
// speedup vs baseline: 1.4410x; 1.4410x over previous
#include <cuda_runtime.h>

// MSFNO1d: B=32, L=4096, H=64, NL=4, modes {512,1024,2048}
#define BB 32
#define HH 64
#define LL 4096
#define NF 2048

typedef unsigned long long ull;

// ---- scratch ----
__device__ float  g_v[BB*HH*LL];
__device__ float  g_s[BB*HH*LL];
__device__ float2 g_X[HH*BB*NF];          // rfft(v)  [i][b][f]
__device__ float2 g_Y[HH*BB*NF];          // mixed    [o][b][f]
__device__ float2 g_twF[2048];            // e^{-2pi i k/2048}, k<2048
__device__ float2 g_tw4096[2048];         // e^{-2pi i k/4096}

// ---- helpers ----
__device__ __forceinline__ float2 cmul(float2 a, float2 b){
    return make_float2(a.x*b.x - a.y*b.y, a.x*b.y + a.y*b.x);
}
__device__ __forceinline__ float2 cadd(float2 a, float2 b){ return make_float2(a.x+b.x, a.y+b.y); }
__device__ __forceinline__ float2 csub(float2 a, float2 b){ return make_float2(a.x-b.x, a.y-b.y); }
__device__ __forceinline__ ull pack2(float lo, float hi){
    ull r; asm("mov.b64 %0,{%1,%2};" : "=l"(r) : "f"(lo), "f"(hi)); return r;
}
__device__ __forceinline__ float2 unpack2(ull v){
    float2 r; asm("mov.b64 {%0,%1},%2;" : "=f"(r.x), "=f"(r.y) : "l"(v)); return r;
}
__device__ __forceinline__ void fma2(ull &acc, ull a, ull b){
    asm("fma.rn.f32x2 %0,%1,%2,%0;" : "+l"(acc) : "l"(a), "l"(b));
}
__device__ __forceinline__ float gelu_tanh(float x){
    float x3 = x*x*x;
    return 0.5f*x*(1.0f + tanhf(0.7978845608028654f*(x + 0.044715f*x3)));
}

// ---- twiddle init ----
__global__ void init_tw_kernel(){
    int k = blockIdx.x*256 + threadIdx.x;
    if (k < 2048){
        double s, c; sincospi(-2.0*(double)k/2048.0, &s, &c);
        g_twF[k] = make_float2((float)c, (float)s);
        double s2, c2; sincospi(-2.0*(double)k/4096.0, &s2, &c2);
        g_tw4096[k] = make_float2((float)c2, (float)s2);
    }
}

// ---- encoder ----
__global__ void encoder_kernel(const float* __restrict__ u, const float* __restrict__ x,
                               const float* __restrict__ ew, const float* __restrict__ eb){
    int b = blockIdx.y;
    int t = blockIdx.x*256 + threadIdx.x;
    float xv = x[(size_t)b*LL + t];
    float u0 = u[((size_t)b*3 + 0)*LL + t];
    float u1 = u[((size_t)b*3 + 1)*LL + t];
    float u2 = u[((size_t)b*3 + 2)*LL + t];
    #pragma unroll 4
    for (int h = 0; h < HH; h++){
        float r = eb[h] + ew[h*4+0]*xv + ew[h*4+1]*u0 + ew[h*4+2]*u1 + ew[h*4+3]*u2;
        g_v[((size_t)b*HH + h)*LL + t] = r;
    }
}

// ===================== Stockham radix-8 FFT (N=2048, 256 threads) =====================
// element-index -> smem slot swizzles (writer and reader must agree per buffer generation)
template<int MODE> __device__ __forceinline__ int swz(int a){
    if (MODE==1) return a ^ (((a>>3) ^ (a>>6)) & 7);     // gen A
    if (MODE==2) return a ^ (((a>>6) & 7) << 3);         // gen B
    return a;                                            // identity
}

// radix-8 DIF butterfly: c[k] = sum_j x[j] * e^{-2pi i jk/8}
__device__ __forceinline__ void radix8(const float2* x, float2* c){
    const float r = 0.70710678118654752f;
    float2 y0 = cadd(x[0],x[4]), y4 = csub(x[0],x[4]);
    float2 y1 = cadd(x[1],x[5]), t5 = csub(x[1],x[5]);
    float2 y2 = cadd(x[2],x[6]), t6 = csub(x[2],x[6]);
    float2 y3 = cadd(x[3],x[7]), t7 = csub(x[3],x[7]);
    float2 y5 = make_float2(r*(t5.x+t5.y), r*(t5.y-t5.x));   // *W8^1
    float2 y6 = make_float2(t6.y, -t6.x);                    // *W8^2 = -i
    float2 y7 = make_float2(r*(t7.y-t7.x), -r*(t7.x+t7.y));  // *W8^3
    float2 z0 = cadd(y0,y2), z2 = csub(y0,y2);
    float2 z1 = cadd(y1,y3), t3 = csub(y1,y3);
    float2 z3 = make_float2(t3.y, -t3.x);
    float2 z4 = cadd(y4,y6), z6 = csub(y4,y6);
    float2 z5 = cadd(y5,y7), u7 = csub(y5,y7);
    float2 z7 = make_float2(u7.y, -u7.x);
    c[0] = cadd(z0,z1); c[4] = csub(z0,z1);
    c[2] = cadd(z2,z3); c[6] = csub(z2,z3);
    c[1] = cadd(z4,z5); c[5] = csub(z4,z5);
    c[3] = cadd(z6,z7); c[7] = csub(z6,z7);
}

// generic smem->smem radix-8 stage: s = 1<<LOGS, m = 2048/(8*s) handled implicitly
template<int LOGS, int TSTR, int SWIN, int SWOUT>
__device__ __forceinline__ void stage8s(const float* ri, const float* im,
                                        float* ro, float* io, int tid){
    int q = tid & ((1<<LOGS)-1);
    int p = tid >> LOGS;
    int base = q + (p << LOGS);
    float2 a[8], c[8];
    #pragma unroll
    for (int j = 0; j < 8; j++){
        int s = swz<SWIN>(base + 256*j);
        a[j] = make_float2(ri[s], im[s]);
    }
    radix8(a, c);
    #pragma unroll
    for (int k = 1; k < 8; k++) c[k] = cmul(c[k], g_twF[p*k*TSTR]);
    #pragma unroll
    for (int k = 0; k < 8; k++){
        int s = swz<SWOUT>(q + ((8*p + k) << LOGS));
        ro[s] = c[k].x; io[s] = c[k].y;
    }
}

// stage1 reading packed complex directly from gmem (s=1, p=tid)
__device__ __forceinline__ void stage8g(const float2* __restrict__ src,
                                        float* ro, float* io, int tid){
    float2 a[8], c[8];
    #pragma unroll
    for (int j = 0; j < 8; j++) a[j] = src[tid + 256*j];
    radix8(a, c);
    #pragma unroll
    for (int k = 1; k < 8; k++) c[k] = cmul(c[k], g_twF[tid*k]);
    #pragma unroll
    for (int k = 0; k < 8; k++){
        int s = swz<1>(8*tid + k);
        ro[s] = c[k].x; io[s] = c[k].y;
    }
}

// final radix-4 stage: s=512, m=1 (no twiddle); identity layouts both sides
__device__ __forceinline__ void stage4s(const float* ri, const float* im,
                                        float* ro, float* io, int tid){
    #pragma unroll
    for (int h = 0; h < 2; h++){
        int q = tid + 256*h;
        float2 x0 = make_float2(ri[q],      im[q]);
        float2 x1 = make_float2(ri[q+512],  im[q+512]);
        float2 x2 = make_float2(ri[q+1024], im[q+1024]);
        float2 x3 = make_float2(ri[q+1536], im[q+1536]);
        float2 y0 = cadd(x0,x2), y2 = csub(x0,x2);
        float2 y1 = cadd(x1,x3), t3 = csub(x1,x3);
        float2 y3 = make_float2(t3.y, -t3.x);
        float2 c0 = cadd(y0,y1), c2 = csub(y0,y1);
        float2 c1 = cadd(y2,y3), c3 = csub(y2,y3);
        ro[q]      = c0.x; io[q]      = c0.y;
        ro[q+512]  = c1.x; io[q+512]  = c1.y;
        ro[q+1024] = c2.x; io[q+1024] = c2.y;
        ro[q+1536] = c3.x; io[q+1536] = c3.y;
    }
}

// ---- forward rfft: v row (4096 real) -> 2048 complex bins ----
__global__ __launch_bounds__(256) void fft_fwd_kernel(){
    __shared__ float r0[2048], i0[2048], r1[2048], i1[2048];
    int b = blockIdx.x, ch = blockIdx.y;
    int tid = threadIdx.x;
    const float2* src = (const float2*)(g_v + ((size_t)b*HH + ch)*LL);  // z[n]=v[2n]+i v[2n+1]
    stage8g(src, r0, i0, tid);                       // gmem -> gen A (buf0)
    __syncthreads();
    stage8s<3,8,1,2>(r0, i0, r1, i1, tid);           // gen A -> gen B (buf1)
    __syncthreads();
    stage8s<6,64,2,0>(r1, i1, r0, i0, tid);          // gen B -> natural (buf0)
    __syncthreads();
    stage4s(r0, i0, r1, i1, tid);                    // natural (buf1)
    __syncthreads();
    float2* dst = g_X + ((size_t)ch*BB + b)*NF;
    for (int k = tid; k < 2048; k += 256){
        float2 Zk = make_float2(r1[k], i1[k]);
        int kn = (2048 - k) & 2047;
        float2 Zn = make_float2(r1[kn], i1[kn]);
        float2 Fe = make_float2(0.5f*(Zk.x + Zn.x),  0.5f*(Zk.y - Zn.y));
        float2 Fo = make_float2(0.5f*(Zk.y + Zn.y), -0.5f*(Zk.x - Zn.x));
        float2 t  = cmul(g_tw4096[k], Fo);
        dst[k] = make_float2(Fe.x + t.x, Fe.y + t.y);
    }
}

// ---- inverse rfft (n=4096, bins>=2048 zero) + bias -> g_s ----
__global__ __launch_bounds__(256) void fft_inv_kernel(const float* __restrict__ sb0,
                                                      const float* __restrict__ sb1,
                                                      const float* __restrict__ sb2, int l){
    __shared__ float r0[2048], i0[2048], r1[2048], i1[2048];
    int b = blockIdx.x, o = blockIdx.y;
    int tid = threadIdx.x;
    const float2* src = g_Y + ((size_t)o*BB + b)*NF;
    for (int k = tid; k < 2048; k += 256){
        float2 Xk = src[k];
        float2 Xn;
        if (k == 0){ Xk.y = 0.0f; Xn = make_float2(0.0f, 0.0f); }
        else        { Xn = src[2048 - k]; }
        float2 Fe = make_float2(0.5f*(Xk.x + Xn.x), 0.5f*(Xk.y - Xn.y));
        float2 D  = make_float2(0.5f*(Xk.x - Xn.x), 0.5f*(Xk.y + Xn.y));
        float2 w  = g_tw4096[k];
        float2 Fo = make_float2(D.x*w.x + D.y*w.y, D.y*w.x - D.x*w.y);
        r0[k] =  Fe.x - Fo.y;
        i0[k] = -(Fe.y + Fo.x);       // conjugate -> forward FFT computes IFFT
    }
    __syncthreads();
    stage8s<0,1,0,1>(r0, i0, r1, i1, tid);
    __syncthreads();
    stage8s<3,8,1,2>(r1, i1, r0, i0, tid);
    __syncthreads();
    stage8s<6,64,2,0>(r0, i0, r1, i1, tid);
    __syncthreads();
    stage4s(r1, i1, r0, i0, tid);
    __syncthreads();
    float bias = sb0[l*HH + o] + sb1[l*HH + o] + sb2[l*HH + o];
    float2* dst = (float2*)(g_s + ((size_t)b*HH + o)*LL);
    const float sc = 1.0f/2048.0f;
    for (int n = tid; n < 2048; n += 256){
        dst[n] = make_float2(r0[n]*sc + bias, -i0[n]*sc + bias);
    }
}

// ===================== spectral mixing =====================
// Y[b,o,f] = sum_i X[b,i,f] * Wsum[i,o,f]; i-chunked by 8, W staged in smem.
// grid: (o-block fastest) so the 8 o-blocks sharing an f-tile are co-resident -> X hits L2.
__global__ __launch_bounds__(512) void spec_gemm_kernel(const float* __restrict__ w0,
                                                        const float* __restrict__ w1,
                                                        const float* __restrict__ w2, int l){
    __shared__ float2 Wp[8][8][32];   // [ii][o][lane] summed weight
    __shared__ float2 Wn[8][8][32];   // (-im, re)
    int o0 = blockIdx.x * 8;
    int f0 = blockIdx.y * 32;
    int tid  = threadIdx.x;
    int lane = tid & 31;
    int g    = tid >> 5;
    int b0   = (g & 7) * 4;
    int oo   = (g >> 3) * 4;
    bool p1 = (f0 < 1024), p0 = (f0 < 512);
    const float2* W2p = (const float2*)w2 + (size_t)l*HH*HH*2048;
    const float2* W1p = (const float2*)w1 + (size_t)l*HH*HH*1024;
    const float2* W0p = (const float2*)w0 + (size_t)l*HH*HH*512;

    ull acc[4][4];
    #pragma unroll
    for (int bi = 0; bi < 4; bi++)
        #pragma unroll
        for (int oi = 0; oi < 4; oi++) acc[bi][oi] = 0ull;

    for (int i0 = 0; i0 < HH; i0 += 8){
        __syncthreads();
        #pragma unroll
        for (int r = 0; r < 4; r++){
            int idx = tid + 512*r;
            int ii = idx >> 8, o = (idx >> 5) & 7, ln = idx & 31;
            size_t base = (size_t)(i0+ii)*HH + (o0 + o);
            float2 wv = W2p[base*2048 + f0 + ln];
            if (p1){ float2 a = W1p[base*1024 + f0 + ln]; wv.x += a.x; wv.y += a.y; }
            if (p0){ float2 a = W0p[base*512  + f0 + ln]; wv.x += a.x; wv.y += a.y; }
            Wp[ii][o][ln] = wv;
            Wn[ii][o][ln] = make_float2(-wv.y, wv.x);
        }
        __syncthreads();
        #pragma unroll
        for (int ii = 0; ii < 8; ii++){
            int i = i0 + ii;
            ull xr[4], xi[4];
            #pragma unroll
            for (int bi = 0; bi < 4; bi++){
                float2 xv = __ldg(&g_X[((size_t)i*BB + b0 + bi)*NF + f0 + lane]);
                xr[bi] = pack2(xv.x, xv.x);
                xi[bi] = pack2(xv.y, xv.y);
            }
            #pragma unroll
            for (int oi = 0; oi < 4; oi++){
                ull wp = *reinterpret_cast<const ull*>(&Wp[ii][oo+oi][lane]);
                ull wn = *reinterpret_cast<const ull*>(&Wn[ii][oo+oi][lane]);
                #pragma unroll
                for (int bi = 0; bi < 4; bi++){
                    fma2(acc[bi][oi], xr[bi], wp);
                    fma2(acc[bi][oi], xi[bi], wn);
                }
            }
        }
    }
    #pragma unroll
    for (int bi = 0; bi < 4; bi++)
        #pragma unroll
        for (int oi = 0; oi < 4; oi++){
            float2 r = unpack2(acc[bi][oi]);
            g_Y[((size_t)(o0 + oo + oi)*BB + b0 + bi)*NF + f0 + lane] = r;
        }
}

// ---- pointwise: v += conv2(gelu(conv1(s))) ----
__global__ __launch_bounds__(256) void pointwise_kernel(const float* __restrict__ w1,
                                                        const float* __restrict__ b1,
                                                        const float* __restrict__ w2,
                                                        const float* __restrict__ b2, int l){
    int b  = blockIdx.y;
    int t0 = blockIdx.x * 64;
    __shared__ float ss[64][64];
    __shared__ float hh[64][64];
    __shared__ float Wb[64][64];
    int tid = threadIdx.x;
    for (int idx = tid; idx < 4096; idx += 256) Wb[idx >> 6][idx & 63] = w1[(size_t)l*4096 + idx];
    for (int idx = tid; idx < 4096; idx += 256)
        ss[idx >> 6][idx & 63] = g_s[((size_t)b*HH + (idx >> 6))*LL + t0 + (idx & 63)];
    __syncthreads();

    int tp = tid & 31;
    int oc = tid >> 5;
    #pragma unroll
    for (int oi = 0; oi < 8; oi++){
        int o = oc*8 + oi;
        float bb = b1[l*HH + o];
        ull acc = pack2(bb, bb);
        #pragma unroll 8
        for (int i = 0; i < 64; i++){
            float w = Wb[o][i];
            ull sv = *(const ull*)&ss[i][2*tp];
            fma2(acc, pack2(w, w), sv);
        }
        float2 a = unpack2(acc);
        hh[o][2*tp]   = gelu_tanh(a.x);
        hh[o][2*tp+1] = gelu_tanh(a.y);
    }
    __syncthreads();
    for (int idx = tid; idx < 4096; idx += 256) Wb[idx >> 6][idx & 63] = w2[(size_t)l*4096 + idx];
    __syncthreads();
    #pragma unroll
    for (int ci = 0; ci < 8; ci++){
        int c = oc*8 + ci;
        float bb = b2[l*HH + c];
        ull acc = pack2(bb, bb);
        #pragma unroll 8
        for (int o = 0; o < 64; o++){
            float w = Wb[c][o];
            ull hv = *(const ull*)&hh[o][2*tp];
            fma2(acc, pack2(w, w), hv);
        }
        float2 a = unpack2(acc);
        float2* vp = (float2*)(g_v + ((size_t)b*HH + c)*LL + t0 + 2*tp);
        float2 vv = *vp;
        vv.x += a.x; vv.y += a.y;
        *vp = vv;
    }
}

// ---- decoder ----
__global__ void decoder_kernel(const float* __restrict__ dw, const float* __restrict__ db,
                               float* __restrict__ out){
    int b = blockIdx.y;
    int t = blockIdx.x*256 + threadIdx.x;
    float acc = db[0];
    #pragma unroll 8
    for (int h = 0; h < HH; h++)
        acc += dw[h] * g_v[((size_t)b*HH + h)*LL + t];
    out[(size_t)b*LL + t] = acc;
}

extern "C" void kernel_launch(void* const* d_in, const int* in_sizes, int n_in,
                              void* d_out, int out_size){
    const float* u     = (const float*)d_in[0];
    const float* x     = (const float*)d_in[1];
    const float* enc_w = (const float*)d_in[2];
    const float* enc_b = (const float*)d_in[3];
    const float* dec_w = (const float*)d_in[4];
    const float* dec_b = (const float*)d_in[5];
    const float* c1w   = (const float*)d_in[6];
    const float* c1b   = (const float*)d_in[7];
    const float* c2w   = (const float*)d_in[8];
    const float* c2b   = (const float*)d_in[9];
    const float* sw0   = (const float*)d_in[10];
    const float* sb0   = (const float*)d_in[11];
    const float* sw1   = (const float*)d_in[12];
    const float* sb1   = (const float*)d_in[13];
    const float* sw2   = (const float*)d_in[14];
    const float* sb2   = (const float*)d_in[15];
    float* out = (float*)d_out;

    init_tw_kernel<<<8, 256>>>();
    encoder_kernel<<<dim3(LL/256, BB), 256>>>(u, x, enc_w, enc_b);
    for (int l = 0; l < 4; l++){
        fft_fwd_kernel<<<dim3(BB, HH), 256>>>();
        spec_gemm_kernel<<<dim3(HH/8, NF/32), 512>>>(sw0, sw1, sw2, l);
        fft_inv_kernel<<<dim3(BB, HH), 256>>>(sb0, sb1, sb2, l);
        pointwise_kernel<<<dim3(LL/64, BB), 256>>>(c1w, c1b, c2w, c2b, l);
    }
    decoder_kernel<<<dim3(LL/256, BB), 256>>>(dec_w, dec_b, out);
}

// round 3
// speedup vs baseline: 2.5423x; 1.7643x over previous
#include <cuda_runtime.h>

// MSFNO1d: B=32, L=4096, H=64, NL=4, modes {512,1024,2048}
#define BB 32
#define HH 64
#define LL 4096
#define NF 2048

typedef unsigned long long ull;

// ---- scratch ----
__device__ float  g_v[BB*HH*LL];
__device__ float  g_s[BB*HH*LL];
__device__ float2 g_X[HH*BB*NF];          // rfft(v)  [i][b][f]
__device__ float2 g_Y[HH*BB*NF];          // mixed    [o][b][f]
__device__ float2 g_twF[2048];            // e^{-2pi i k/2048}
__device__ float2 g_tw4096[2048];         // e^{-2pi i k/4096}

// ---- helpers ----
__device__ __forceinline__ float2 cmul(float2 a, float2 b){
    return make_float2(a.x*b.x - a.y*b.y, a.x*b.y + a.y*b.x);
}
__device__ __forceinline__ float2 cadd(float2 a, float2 b){ return make_float2(a.x+b.x, a.y+b.y); }
__device__ __forceinline__ float2 csub(float2 a, float2 b){ return make_float2(a.x-b.x, a.y-b.y); }
__device__ __forceinline__ ull pack2(float lo, float hi){
    ull r; asm("mov.b64 %0,{%1,%2};" : "=l"(r) : "f"(lo), "f"(hi)); return r;
}
__device__ __forceinline__ float2 unpack2(ull v){
    float2 r; asm("mov.b64 {%0,%1},%2;" : "=f"(r.x), "=f"(r.y) : "l"(v)); return r;
}
__device__ __forceinline__ void fma2(ull &acc, ull a, ull b){
    asm("fma.rn.f32x2 %0,%1,%2,%0;" : "+l"(acc) : "l"(a), "l"(b));
}
__device__ __forceinline__ float gelu_tanh(float x){
    float x3 = x*x*x;
    return 0.5f*x*(1.0f + tanhf(0.7978845608028654f*(x + 0.044715f*x3)));
}

// ---- twiddle init ----
__global__ void init_tw_kernel(){
    int k = blockIdx.x*256 + threadIdx.x;
    if (k < 2048){
        double s, c; sincospi(-2.0*(double)k/2048.0, &s, &c);
        g_twF[k] = make_float2((float)c, (float)s);
        double s2, c2; sincospi(-2.0*(double)k/4096.0, &s2, &c2);
        g_tw4096[k] = make_float2((float)c2, (float)s2);
    }
}

// ---- encoder ----
__global__ void encoder_kernel(const float* __restrict__ u, const float* __restrict__ x,
                               const float* __restrict__ ew, const float* __restrict__ eb){
    int b = blockIdx.y;
    int t = blockIdx.x*256 + threadIdx.x;
    float xv = x[(size_t)b*LL + t];
    float u0 = u[((size_t)b*3 + 0)*LL + t];
    float u1 = u[((size_t)b*3 + 1)*LL + t];
    float u2 = u[((size_t)b*3 + 2)*LL + t];
    #pragma unroll 4
    for (int h = 0; h < HH; h++){
        float r = eb[h] + ew[h*4+0]*xv + ew[h*4+1]*u0 + ew[h*4+2]*u1 + ew[h*4+3]*u2;
        g_v[((size_t)b*HH + h)*LL + t] = r;
    }
}

// ===================== Stockham radix-8 FFT (N=2048, 256 threads) =====================
template<int MODE> __device__ __forceinline__ int swz(int a){
    if (MODE==1) return a ^ (((a>>3) ^ (a>>6)) & 7);     // gen A
    if (MODE==2) return a ^ (((a>>6) & 7) << 3);         // gen B
    return a;                                            // identity
}

// radix-8 DIF butterfly: c[k] = sum_j x[j] * e^{-2pi i jk/8}
__device__ __forceinline__ void radix8(const float2* x, float2* c){
    const float r = 0.70710678118654752f;
    float2 y0 = cadd(x[0],x[4]), y4 = csub(x[0],x[4]);
    float2 y1 = cadd(x[1],x[5]), t5 = csub(x[1],x[5]);
    float2 y2 = cadd(x[2],x[6]), t6 = csub(x[2],x[6]);
    float2 y3 = cadd(x[3],x[7]), t7 = csub(x[3],x[7]);
    float2 y5 = make_float2(r*(t5.x+t5.y), r*(t5.y-t5.x));
    float2 y6 = make_float2(t6.y, -t6.x);
    float2 y7 = make_float2(r*(t7.y-t7.x), -r*(t7.x+t7.y));
    float2 z0 = cadd(y0,y2), z2 = csub(y0,y2);
    float2 z1 = cadd(y1,y3), t3 = csub(y1,y3);
    float2 z3 = make_float2(t3.y, -t3.x);
    float2 z4 = cadd(y4,y6), z6 = csub(y4,y6);
    float2 z5 = cadd(y5,y7), u7 = csub(y5,y7);
    float2 z7 = make_float2(u7.y, -u7.x);
    c[0] = cadd(z0,z1); c[4] = csub(z0,z1);
    c[2] = cadd(z2,z3); c[6] = csub(z2,z3);
    c[1] = cadd(z4,z5); c[5] = csub(z4,z5);
    c[3] = cadd(z6,z7); c[7] = csub(z6,z7);
}

// twiddle by chain: c[k] *= w1^k  (1 coalesced load instead of 7 strided ones)
__device__ __forceinline__ void twchain(float2* c, float2 w1){
    float2 wk = w1;
    c[1] = cmul(c[1], wk);
    #pragma unroll
    for (int k = 2; k < 8; k++){ wk = cmul(wk, w1); c[k] = cmul(c[k], wk); }
}

template<int LOGS, int TSTR, int SWIN, int SWOUT>
__device__ __forceinline__ void stage8s(const float* ri, const float* im,
                                        float* ro, float* io, int tid){
    int q = tid & ((1<<LOGS)-1);
    int p = tid >> LOGS;
    int base = q + (p << LOGS);
    float2 a[8], c[8];
    #pragma unroll
    for (int j = 0; j < 8; j++){
        int s = swz<SWIN>(base + 256*j);
        a[j] = make_float2(ri[s], im[s]);
    }
    radix8(a, c);
    twchain(c, g_twF[p*TSTR]);
    #pragma unroll
    for (int k = 0; k < 8; k++){
        int s = swz<SWOUT>(q + ((8*p + k) << LOGS));
        ro[s] = c[k].x; io[s] = c[k].y;
    }
}

__device__ __forceinline__ void stage8g(const float2* __restrict__ src,
                                        float* ro, float* io, int tid){
    float2 a[8], c[8];
    #pragma unroll
    for (int j = 0; j < 8; j++) a[j] = src[tid + 256*j];
    radix8(a, c);
    twchain(c, g_twF[tid]);
    #pragma unroll
    for (int k = 0; k < 8; k++){
        int s = swz<1>(8*tid + k);
        ro[s] = c[k].x; io[s] = c[k].y;
    }
}

__device__ __forceinline__ void stage4s(const float* ri, const float* im,
                                        float* ro, float* io, int tid){
    #pragma unroll
    for (int h = 0; h < 2; h++){
        int q = tid + 256*h;
        float2 x0 = make_float2(ri[q],      im[q]);
        float2 x1 = make_float2(ri[q+512],  im[q+512]);
        float2 x2 = make_float2(ri[q+1024], im[q+1024]);
        float2 x3 = make_float2(ri[q+1536], im[q+1536]);
        float2 y0 = cadd(x0,x2), y2 = csub(x0,x2);
        float2 y1 = cadd(x1,x3), t3 = csub(x1,x3);
        float2 y3 = make_float2(t3.y, -t3.x);
        float2 c0 = cadd(y0,y1), c2 = csub(y0,y1);
        float2 c1 = cadd(y2,y3), c3 = csub(y2,y3);
        ro[q]      = c0.x; io[q]      = c0.y;
        ro[q+512]  = c1.x; io[q+512]  = c1.y;
        ro[q+1024] = c2.x; io[q+1024] = c2.y;
        ro[q+1536] = c3.x; io[q+1536] = c3.y;
    }
}

// ---- forward rfft ----
__global__ __launch_bounds__(256) void fft_fwd_kernel(){
    __shared__ float r0[2048], i0[2048], r1[2048], i1[2048];
    int b = blockIdx.x, ch = blockIdx.y;
    int tid = threadIdx.x;
    const float2* src = (const float2*)(g_v + ((size_t)b*HH + ch)*LL);
    stage8g(src, r0, i0, tid);
    __syncthreads();
    stage8s<3,8,1,2>(r0, i0, r1, i1, tid);
    __syncthreads();
    stage8s<6,64,2,0>(r1, i1, r0, i0, tid);
    __syncthreads();
    stage4s(r0, i0, r1, i1, tid);
    __syncthreads();
    float2* dst = g_X + ((size_t)ch*BB + b)*NF;
    for (int k = tid; k < 2048; k += 256){
        float2 Zk = make_float2(r1[k], i1[k]);
        int kn = (2048 - k) & 2047;
        float2 Zn = make_float2(r1[kn], i1[kn]);
        float2 Fe = make_float2(0.5f*(Zk.x + Zn.x),  0.5f*(Zk.y - Zn.y));
        float2 Fo = make_float2(0.5f*(Zk.y + Zn.y), -0.5f*(Zk.x - Zn.x));
        float2 t  = cmul(g_tw4096[k], Fo);
        dst[k] = make_float2(Fe.x + t.x, Fe.y + t.y);
    }
}

// ---- inverse rfft + bias -> g_s ----
__global__ __launch_bounds__(256) void fft_inv_kernel(const float* __restrict__ sb0,
                                                      const float* __restrict__ sb1,
                                                      const float* __restrict__ sb2, int l){
    __shared__ float r0[2048], i0[2048], r1[2048], i1[2048];
    int b = blockIdx.x, o = blockIdx.y;
    int tid = threadIdx.x;
    const float2* src = g_Y + ((size_t)o*BB + b)*NF;
    for (int k = tid; k < 2048; k += 256){
        float2 Xk = src[k];
        float2 Xn;
        if (k == 0){ Xk.y = 0.0f; Xn = make_float2(0.0f, 0.0f); }
        else        { Xn = src[2048 - k]; }
        float2 Fe = make_float2(0.5f*(Xk.x + Xn.x), 0.5f*(Xk.y - Xn.y));
        float2 D  = make_float2(0.5f*(Xk.x - Xn.x), 0.5f*(Xk.y + Xn.y));
        float2 w  = g_tw4096[k];
        float2 Fo = make_float2(D.x*w.x + D.y*w.y, D.y*w.x - D.x*w.y);
        r0[k] =  Fe.x - Fo.y;
        i0[k] = -(Fe.y + Fo.x);
    }
    __syncthreads();
    stage8s<0,1,0,1>(r0, i0, r1, i1, tid);
    __syncthreads();
    stage8s<3,8,1,2>(r1, i1, r0, i0, tid);
    __syncthreads();
    stage8s<6,64,2,0>(r0, i0, r1, i1, tid);
    __syncthreads();
    stage4s(r1, i1, r0, i0, tid);
    __syncthreads();
    float bias = sb0[l*HH + o] + sb1[l*HH + o] + sb2[l*HH + o];
    float2* dst = (float2*)(g_s + ((size_t)b*HH + o)*LL);
    const float sc = 1.0f/2048.0f;
    for (int n = tid; n < 2048; n += 256){
        dst[n] = make_float2(r0[n]*sc + bias, -i0[n]*sc + bias);
    }
}

// ===================== spectral mixing =====================
// Y[b,o,f] = sum_i X[b,i,f]*Wsum[i,o,f]; chunk i by 4; X AND W staged in smem (48KB).
__global__ __launch_bounds__(512) void spec_gemm_kernel(const float* __restrict__ w0,
                                                        const float* __restrict__ w1,
                                                        const float* __restrict__ w2, int l){
    __shared__ float2 Xs[4][32][32];  // [ii][b][f]  32KB
    __shared__ float2 Wp[4][8][32];   // 8KB
    __shared__ float2 Wn[4][8][32];   // 8KB
    int o0 = blockIdx.x * 8;
    int f0 = blockIdx.y * 32;
    int tid  = threadIdx.x;
    int lane = tid & 31;
    int g    = tid >> 5;
    int b0   = (g & 7) * 4;
    int oo   = (g >> 3) * 4;
    bool p1 = (f0 < 1024), p0 = (f0 < 512);
    const float2* W2p = (const float2*)w2 + (size_t)l*HH*HH*2048;
    const float2* W1p = (const float2*)w1 + (size_t)l*HH*HH*1024;
    const float2* W0p = (const float2*)w0 + (size_t)l*HH*HH*512;

    ull acc[4][4];
    #pragma unroll
    for (int bi = 0; bi < 4; bi++)
        #pragma unroll
        for (int oi = 0; oi < 4; oi++) acc[bi][oi] = 0ull;

    for (int i0 = 0; i0 < HH; i0 += 4){
        __syncthreads();
        // stage W: 4*8*32 = 1024 float2
        #pragma unroll
        for (int r = 0; r < 2; r++){
            int idx = tid + 512*r;
            int ii = idx >> 8, o = (idx >> 5) & 7, ln = idx & 31;
            size_t base = (size_t)(i0+ii)*HH + (o0 + o);
            float2 wv = W2p[base*2048 + f0 + ln];
            if (p1){ float2 a = W1p[base*1024 + f0 + ln]; wv.x += a.x; wv.y += a.y; }
            if (p0){ float2 a = W0p[base*512  + f0 + ln]; wv.x += a.x; wv.y += a.y; }
            Wp[ii][o][ln] = wv;
            Wn[ii][o][ln] = make_float2(-wv.y, wv.x);
        }
        // stage X: 4*32*32 = 4096 float2
        #pragma unroll
        for (int r = 0; r < 8; r++){
            int idx = tid + 512*r;
            int ii = idx >> 10, bb = (idx >> 5) & 31, ln = idx & 31;
            Xs[ii][bb][ln] = g_X[((size_t)(i0+ii)*BB + bb)*NF + f0 + ln];
        }
        __syncthreads();
        #pragma unroll
        for (int ii = 0; ii < 4; ii++){
            ull xr[4], xi[4];
            #pragma unroll
            for (int bi = 0; bi < 4; bi++){
                float2 xv = Xs[ii][b0+bi][lane];
                xr[bi] = pack2(xv.x, xv.x);
                xi[bi] = pack2(xv.y, xv.y);
            }
            #pragma unroll
            for (int oi = 0; oi < 4; oi++){
                ull wp = *reinterpret_cast<const ull*>(&Wp[ii][oo+oi][lane]);
                ull wn = *reinterpret_cast<const ull*>(&Wn[ii][oo+oi][lane]);
                #pragma unroll
                for (int bi = 0; bi < 4; bi++){
                    fma2(acc[bi][oi], xr[bi], wp);
                    fma2(acc[bi][oi], xi[bi], wn);
                }
            }
        }
    }
    #pragma unroll
    for (int bi = 0; bi < 4; bi++)
        #pragma unroll
        for (int oi = 0; oi < 4; oi++){
            float2 r = unpack2(acc[bi][oi]);
            g_Y[((size_t)(o0 + oo + oi)*BB + b0 + bi)*NF + f0 + lane] = r;
        }
}

// ---- pointwise: v += conv2(gelu(conv1(s))); register-tiled 4o x 8t ----
__global__ __launch_bounds__(256) void pointwise_kernel(const float* __restrict__ w1,
                                                        const float* __restrict__ b1,
                                                        const float* __restrict__ w2,
                                                        const float* __restrict__ b2, int l){
    int b  = blockIdx.y;
    int t0 = blockIdx.x * 128;
    __shared__ float ss[64][128];   // s, then reused for h
    __shared__ float Wb[64][64];
    int tid = threadIdx.x;
    int ts  = tid & 15;             // 16 t-slots, thread covers t = 2*ts + 32*j + {0,1}
    int og  = tid >> 4;             // 16 o-groups x 4 o

    // load s tile (64 x 128 floats)
    #pragma unroll
    for (int r = 0; r < 16; r++){
        int idx = tid + 256*r;                    // over 4096 float2
        int i = idx >> 6, c2 = idx & 63;
        *(float2*)&ss[i][c2*2] = *(const float2*)&g_s[((size_t)b*HH + i)*LL + t0 + c2*2];
    }
    // load W1
    #pragma unroll
    for (int r = 0; r < 16; r++){
        int idx = tid + 256*r;
        Wb[idx >> 6][idx & 63] = w1[(size_t)l*4096 + idx];
    }
    __syncthreads();

    ull acc[4][4];
    #pragma unroll
    for (int oi = 0; oi < 4; oi++){
        float bv = b1[l*HH + og*4 + oi];
        #pragma unroll
        for (int j = 0; j < 4; j++) acc[oi][j] = pack2(bv, bv);
    }
    for (int i = 0; i < 64; i++){
        ull sv[4];
        #pragma unroll
        for (int j = 0; j < 4; j++) sv[j] = *(const ull*)&ss[i][2*ts + 32*j];
        #pragma unroll
        for (int oi = 0; oi < 4; oi++){
            float w = Wb[og*4 + oi][i];
            ull wp = pack2(w, w);
            #pragma unroll
            for (int j = 0; j < 4; j++) fma2(acc[oi][j], wp, sv[j]);
        }
    }
    __syncthreads();   // everyone done reading ss
    #pragma unroll
    for (int oi = 0; oi < 4; oi++)
        #pragma unroll
        for (int j = 0; j < 4; j++){
            float2 a = unpack2(acc[oi][j]);
            ss[og*4 + oi][2*ts + 32*j]     = gelu_tanh(a.x);
            ss[og*4 + oi][2*ts + 32*j + 1] = gelu_tanh(a.y);
        }
    // load W2
    #pragma unroll
    for (int r = 0; r < 16; r++){
        int idx = tid + 256*r;
        Wb[idx >> 6][idx & 63] = w2[(size_t)l*4096 + idx];
    }
    __syncthreads();

    ull acc2[4][4];
    #pragma unroll
    for (int ci = 0; ci < 4; ci++){
        float bv = b2[l*HH + og*4 + ci];
        #pragma unroll
        for (int j = 0; j < 4; j++) acc2[ci][j] = pack2(bv, bv);
    }
    for (int o = 0; o < 64; o++){
        ull hv[4];
        #pragma unroll
        for (int j = 0; j < 4; j++) hv[j] = *(const ull*)&ss[o][2*ts + 32*j];
        #pragma unroll
        for (int ci = 0; ci < 4; ci++){
            float w = Wb[og*4 + ci][o];
            ull wp = pack2(w, w);
            #pragma unroll
            for (int j = 0; j < 4; j++) fma2(acc2[ci][j], wp, hv[j]);
        }
    }
    #pragma unroll
    for (int ci = 0; ci < 4; ci++){
        int c = og*4 + ci;
        #pragma unroll
        for (int j = 0; j < 4; j++){
            float2 a = unpack2(acc2[ci][j]);
            float2* vp = (float2*)(g_v + ((size_t)b*HH + c)*LL + t0 + 2*ts + 32*j);
            float2 vv = *vp;
            vv.x += a.x; vv.y += a.y;
            *vp = vv;
        }
    }
}

// ---- decoder ----
__global__ void decoder_kernel(const float* __restrict__ dw, const float* __restrict__ db,
                               float* __restrict__ out){
    int b = blockIdx.y;
    int t = blockIdx.x*256 + threadIdx.x;
    float acc = db[0];
    #pragma unroll 8
    for (int h = 0; h < HH; h++)
        acc += dw[h] * g_v[((size_t)b*HH + h)*LL + t];
    out[(size_t)b*LL + t] = acc;
}

extern "C" void kernel_launch(void* const* d_in, const int* in_sizes, int n_in,
                              void* d_out, int out_size){
    const float* u     = (const float*)d_in[0];
    const float* x     = (const float*)d_in[1];
    const float* enc_w = (const float*)d_in[2];
    const float* enc_b = (const float*)d_in[3];
    const float* dec_w = (const float*)d_in[4];
    const float* dec_b = (const float*)d_in[5];
    const float* c1w   = (const float*)d_in[6];
    const float* c1b   = (const float*)d_in[7];
    const float* c2w   = (const float*)d_in[8];
    const float* c2b   = (const float*)d_in[9];
    const float* sw0   = (const float*)d_in[10];
    const float* sb0   = (const float*)d_in[11];
    const float* sw1   = (const float*)d_in[12];
    const float* sb1   = (const float*)d_in[13];
    const float* sw2   = (const float*)d_in[14];
    const float* sb2   = (const float*)d_in[15];
    float* out = (float*)d_out;

    init_tw_kernel<<<8, 256>>>();
    encoder_kernel<<<dim3(LL/256, BB), 256>>>(u, x, enc_w, enc_b);
    for (int l = 0; l < 4; l++){
        fft_fwd_kernel<<<dim3(BB, HH), 256>>>();
        spec_gemm_kernel<<<dim3(HH/8, NF/32), 512>>>(sw0, sw1, sw2, l);
        fft_inv_kernel<<<dim3(BB, HH), 256>>>(sb0, sb1, sb2, l);
        pointwise_kernel<<<dim3(LL/128, BB), 256>>>(c1w, c1b, c2w, c2b, l);
    }
    decoder_kernel<<<dim3(LL/256, BB), 256>>>(dec_w, dec_b, out);
}